// round 4
// baseline (speedup 1.0000x reference)
#include <cuda_runtime.h>
#include <cuda_bf16.h>

// Problem constants (fixed by the dataset)
#define NNODES 100000
#define NEDGES 1600000
#define DIM    128

// Scratch: __device__ globals (no allocations allowed in kernel_launch).
__device__ float g_deg [NNODES];           // degree, then 1/max(deg,1) in place
__device__ float g_agg0[NNODES * DIM];     // layer-0 aggregation
__device__ float g_agg1[NNODES * DIM];     // layer-1 aggregation
__device__ float g_h   [NNODES * DIM];     // hidden activations

// ---------------------------------------------------------------------------
// Zero scratch accumulators (captured into the graph -> re-zeroed on replay)
// ---------------------------------------------------------------------------
__global__ void zero_all_kernel() {
    const float4 z = make_float4(0.f, 0.f, 0.f, 0.f);
    long i = (long)blockIdx.x * blockDim.x + threadIdx.x;
    long stride = (long)gridDim.x * blockDim.x;
    float4* p0 = reinterpret_cast<float4*>(g_deg);
    float4* p1 = reinterpret_cast<float4*>(g_agg0);
    float4* p2 = reinterpret_cast<float4*>(g_agg1);
    for (long j = i; j < NNODES / 4; j += stride) p0[j] = z;
    for (long j = i; j < (long)NNODES * DIM / 4; j += stride) p1[j] = z;
    for (long j = i; j < (long)NNODES * DIM / 4; j += stride) p2[j] = z;
}

// ---------------------------------------------------------------------------
// Out-degree of src nodes
// ---------------------------------------------------------------------------
__global__ void deg_kernel(const int* __restrict__ src, int E) {
    int i = blockIdx.x * blockDim.x + threadIdx.x;
    if (i < E) atomicAdd(&g_deg[src[i]], 1.0f);
}

__global__ void inv_kernel(int n) {
    int i = blockIdx.x * blockDim.x + threadIdx.x;
    if (i < n) g_deg[i] = 1.0f / fmaxf(g_deg[i], 1.0f);
}

// ---------------------------------------------------------------------------
// Scatter: agg[dst] += feat[src] * inv_deg[src]
// One warp per edge: 32 lanes x float4 = 128 features.
// red.global.add.v4.f32 = fire-and-forget vectorized L2 reduction (sm_90+).
// ---------------------------------------------------------------------------
__global__ void scatter_kernel(const float* __restrict__ feat,
                               const int* __restrict__ src,
                               const int* __restrict__ dst,
                               float* __restrict__ agg, int E) {
    int w = (int)(((long)blockIdx.x * blockDim.x + threadIdx.x) >> 5);
    if (w >= E) return;
    int lane = threadIdx.x & 31;
    int s = __ldg(src + w);
    int d = __ldg(dst + w);
    float sc = __ldg(&g_deg[s]);   // holds 1/max(deg,1)
    float4 v = __ldg(reinterpret_cast<const float4*>(feat) + (long)s * 32 + lane);
    float* p = agg + (long)d * DIM + lane * 4;
    asm volatile("red.global.add.v4.f32 [%0], {%1, %2, %3, %4};"
                 :: "l"(p), "f"(v.x * sc), "f"(v.y * sc), "f"(v.z * sc), "f"(v.w * sc)
                 : "memory");
}

// ---------------------------------------------------------------------------
// Fused concat-GEMM: out[n, j] = act( sum_k [A0 | A1][n, k] * W[j, k] + b[j] )
// W is [128, 256] row-major. BM=BN=128, BK=16, 256 threads, 8x8 per thread.
// The k-chunk boundary (128) is a multiple of BK, so each k-tile reads from
// exactly one of A0/A1 -> no per-element branching.
// ---------------------------------------------------------------------------
template <bool RELU>
__global__ void gemm_concat_kernel(const float* __restrict__ A0,
                                   const float* __restrict__ A1,
                                   const float* __restrict__ W,
                                   const float* __restrict__ bias,
                                   float* __restrict__ out, int n) {
    __shared__ float As[16][128];   // As[k][row]
    __shared__ float Wsh[16][128];  // Wsh[k][col]

    const int tid = threadIdx.x;
    const int tx = tid & 15;        // col group
    const int ty = tid >> 4;        // row group
    const int row0 = blockIdx.x * 128;

    float acc[8][8];
#pragma unroll
    for (int m = 0; m < 8; m++)
#pragma unroll
        for (int nn = 0; nn < 8; nn++) acc[m][nn] = 0.f;

    for (int k0 = 0; k0 < 256; k0 += 16) {
        const float* Aptr = (k0 < 128) ? (A0 + k0) : (A1 + (k0 - 128));

        // Load A tile: 128 rows x 16 k = 512 float4, 2 per thread
#pragma unroll
        for (int i = 0; i < 2; i++) {
            int idx = tid + i * 256;
            int r = idx >> 2, c4 = idx & 3;
            int rg = row0 + r;
            float4 v = make_float4(0.f, 0.f, 0.f, 0.f);
            if (rg < n)
                v = __ldg(reinterpret_cast<const float4*>(Aptr + (long)rg * DIM) + c4);
            As[c4 * 4 + 0][r] = v.x;
            As[c4 * 4 + 1][r] = v.y;
            As[c4 * 4 + 2][r] = v.z;
            As[c4 * 4 + 3][r] = v.w;
        }
        // Load W tile: 128 j x 16 k
#pragma unroll
        for (int i = 0; i < 2; i++) {
            int idx = tid + i * 256;
            int j = idx >> 2, c4 = idx & 3;
            float4 v = __ldg(reinterpret_cast<const float4*>(W + (long)j * 256 + k0) + c4);
            Wsh[c4 * 4 + 0][j] = v.x;
            Wsh[c4 * 4 + 1][j] = v.y;
            Wsh[c4 * 4 + 2][j] = v.z;
            Wsh[c4 * 4 + 3][j] = v.w;
        }
        __syncthreads();

#pragma unroll
        for (int kk = 0; kk < 16; kk++) {
            float4 a0 = *reinterpret_cast<const float4*>(&As[kk][ty * 8]);
            float4 a1 = *reinterpret_cast<const float4*>(&As[kk][ty * 8 + 4]);
            float4 w0 = *reinterpret_cast<const float4*>(&Wsh[kk][tx * 8]);
            float4 w1 = *reinterpret_cast<const float4*>(&Wsh[kk][tx * 8 + 4]);
            float a[8] = {a0.x, a0.y, a0.z, a0.w, a1.x, a1.y, a1.z, a1.w};
            float w[8] = {w0.x, w0.y, w0.z, w0.w, w1.x, w1.y, w1.z, w1.w};
#pragma unroll
            for (int m = 0; m < 8; m++)
#pragma unroll
                for (int nn = 0; nn < 8; nn++) acc[m][nn] = fmaf(a[m], w[nn], acc[m][nn]);
        }
        __syncthreads();
    }

    // Epilogue: bias (+ReLU), vectorized stores
    const int col0 = tx * 8;
    float bv[8];
#pragma unroll
    for (int nn = 0; nn < 8; nn++) bv[nn] = __ldg(&bias[col0 + nn]);

#pragma unroll
    for (int m = 0; m < 8; m++) {
        int r = row0 + ty * 8 + m;
        if (r < n) {
#pragma unroll
            for (int g = 0; g < 2; g++) {
                float4 o;
                o.x = acc[m][g * 4 + 0] + bv[g * 4 + 0];
                o.y = acc[m][g * 4 + 1] + bv[g * 4 + 1];
                o.z = acc[m][g * 4 + 2] + bv[g * 4 + 2];
                o.w = acc[m][g * 4 + 3] + bv[g * 4 + 3];
                if (RELU) {
                    o.x = fmaxf(o.x, 0.f); o.y = fmaxf(o.y, 0.f);
                    o.z = fmaxf(o.z, 0.f); o.w = fmaxf(o.w, 0.f);
                }
                *reinterpret_cast<float4*>(out + (long)r * DIM + col0 + g * 4) = o;
            }
        }
    }
}

// ---------------------------------------------------------------------------
extern "C" void kernel_launch(void* const* d_in, const int* in_sizes, int n_in,
                              void* d_out, int out_size) {
    const float* x   = (const float*)d_in[0];
    const int*   src = (const int*)  d_in[1];
    const int*   dst = (const int*)  d_in[2];
    const float* W0  = (const float*)d_in[3];
    const float* b0  = (const float*)d_in[4];
    const float* W1  = (const float*)d_in[5];
    const float* b1  = (const float*)d_in[6];
    float* out = (float*)d_out;

    const int n = in_sizes[0] / DIM;
    const int E = in_sizes[1];

    float *p_agg0, *p_agg1, *p_h;
    cudaGetSymbolAddress((void**)&p_agg0, g_agg0);
    cudaGetSymbolAddress((void**)&p_agg1, g_agg1);
    cudaGetSymbolAddress((void**)&p_h,    g_h);

    zero_all_kernel<<<4096, 256>>>();
    deg_kernel<<<(E + 255) / 256, 256>>>(src, E);
    inv_kernel<<<(n + 255) / 256, 256>>>(n);

    // One warp (32 threads) per edge -> E*32 total threads.
    const long scatter_threads = (long)E * 32;
    const int scatter_blocks = (int)((scatter_threads + 255) / 256);

    // Layer 0
    scatter_kernel<<<scatter_blocks, 256>>>(x, src, dst, p_agg0, E);
    gemm_concat_kernel<true><<<(n + 127) / 128, 256>>>(x, p_agg0, W0, b0, p_h, n);

    // Layer 1
    scatter_kernel<<<scatter_blocks, 256>>>(p_h, src, dst, p_agg1, E);
    gemm_concat_kernel<false><<<(n + 127) / 128, 256>>>(p_h, p_agg1, W1, b1, out, n);
}

// round 6
// speedup vs baseline: 1.2095x; 1.2095x over previous
#include <cuda_runtime.h>
#include <cuda_bf16.h>

// Problem constants (fixed by the dataset)
#define NNODES 100000
#define NEDGES 1600000
#define DIM    128
#define EPW    4      // edges per warp in scatter

// Scratch: __device__ globals (no allocations allowed in kernel_launch).
__device__ float g_deg [NNODES];           // degree, then 1/max(deg,1) in place
__device__ float g_agg0[NNODES * DIM];     // layer-0 aggregation
__device__ float g_agg1[NNODES * DIM];     // layer-1 aggregation
__device__ float g_h   [NNODES * DIM];     // hidden activations

// ---------------------------------------------------------------------------
// Zero scratch accumulators (captured into the graph -> re-zeroed on replay)
// ---------------------------------------------------------------------------
__global__ void zero_all_kernel() {
    const float4 z = make_float4(0.f, 0.f, 0.f, 0.f);
    long i = (long)blockIdx.x * blockDim.x + threadIdx.x;
    long stride = (long)gridDim.x * blockDim.x;
    float4* p0 = reinterpret_cast<float4*>(g_deg);
    float4* p1 = reinterpret_cast<float4*>(g_agg0);
    float4* p2 = reinterpret_cast<float4*>(g_agg1);
    for (long j = i; j < NNODES / 4; j += stride) p0[j] = z;
    for (long j = i; j < (long)NNODES * DIM / 4; j += stride) p1[j] = z;
    for (long j = i; j < (long)NNODES * DIM / 4; j += stride) p2[j] = z;
}

// ---------------------------------------------------------------------------
// Out-degree of src nodes, then invert
// ---------------------------------------------------------------------------
__global__ void deg_kernel(const int* __restrict__ src, int E) {
    int i = blockIdx.x * blockDim.x + threadIdx.x;
    if (i < E) atomicAdd(&g_deg[src[i]], 1.0f);
}

__global__ void inv_kernel(int n) {
    int i = blockIdx.x * blockDim.x + threadIdx.x;
    if (i < n) g_deg[i] = 1.0f / fmaxf(g_deg[i], 1.0f);
}

// ---------------------------------------------------------------------------
// Scatter: agg[dst] += feat[src] * inv_deg[src]
// One warp per EPW edges. All loads for the batch are issued before any RED
// (MLP = EPW) to lift issue utilization (was 25% with MLP=1).
// ---------------------------------------------------------------------------
__global__ __launch_bounds__(256) void scatter_kernel(
        const float* __restrict__ feat,
        const int* __restrict__ src,
        const int* __restrict__ dst,
        float* __restrict__ agg, int E) {
    const long warp = ((long)blockIdx.x * blockDim.x + threadIdx.x) >> 5;
    const int lane = threadIdx.x & 31;
    const long e0 = warp * EPW;
    if (e0 >= E) return;

    int  s[EPW], d[EPW];
    bool ok[EPW];
#pragma unroll
    for (int i = 0; i < EPW; i++) {
        long e = e0 + i;
        ok[i] = (e < E);
        s[i] = ok[i] ? __ldg(src + e) : 0;
        d[i] = ok[i] ? __ldg(dst + e) : 0;
    }
    float sc[EPW];
#pragma unroll
    for (int i = 0; i < EPW; i++) sc[i] = __ldg(&g_deg[s[i]]);

    float4 v[EPW];
#pragma unroll
    for (int i = 0; i < EPW; i++)
        v[i] = __ldg(reinterpret_cast<const float4*>(feat) + (long)s[i] * 32 + lane);

#pragma unroll
    for (int i = 0; i < EPW; i++) {
        if (!ok[i]) continue;
        float* p = agg + (long)d[i] * DIM + lane * 4;
        asm volatile("red.global.add.v4.f32 [%0], {%1, %2, %3, %4};"
                     :: "l"(p), "f"(v[i].x * sc[i]), "f"(v[i].y * sc[i]),
                        "f"(v[i].z * sc[i]), "f"(v[i].w * sc[i])
                     : "memory");
    }
}

// ---------------------------------------------------------------------------
// Fused concat-GEMM, double-buffered: out[n,j] = act([A0|A1][n,:] . W[j,:] + b[j])
// W is [128, 256] row-major. BM=BN=128, BK=16, 256 threads, 8x8 per thread.
// Tile t+1 is prefetched into registers while tile t computes; two smem
// buffers -> one __syncthreads per k-tile, LDG latency hidden under FFMA.
// ---------------------------------------------------------------------------
template <bool RELU>
__global__ __launch_bounds__(256, 2) void gemm_concat_kernel(
        const float* __restrict__ A0,
        const float* __restrict__ A1,
        const float* __restrict__ W,
        const float* __restrict__ bias,
        float* __restrict__ out, int n) {
    __shared__ float As [2][16][128];   // As[buf][k][row]
    __shared__ float Wsh[2][16][128];   // Wsh[buf][k][col]

    const int tid = threadIdx.x;
    const int tx = tid & 15;        // col group
    const int ty = tid >> 4;        // row group
    const int row0 = blockIdx.x * 128;

    // Per-thread tile-load coordinates (2 float4 per tile for A and W each)
    const int r_  = (tid + 0)   >> 2, c4_  = tid & 3;
    const int r2_ = (tid + 256) >> 2;            // second half: rows 64..127

    auto loadA = [&](int k0, float4 va[2]) {
        const float* Aptr = (k0 < 128) ? (A0 + k0) : (A1 + (k0 - 128));
        int rg0 = row0 + r_, rg1 = row0 + r2_;
        va[0] = make_float4(0.f, 0.f, 0.f, 0.f);
        va[1] = make_float4(0.f, 0.f, 0.f, 0.f);
        if (rg0 < n) va[0] = __ldg(reinterpret_cast<const float4*>(Aptr + (long)rg0 * DIM) + c4_);
        if (rg1 < n) va[1] = __ldg(reinterpret_cast<const float4*>(Aptr + (long)rg1 * DIM) + c4_);
    };
    auto loadW = [&](int k0, float4 vw[2]) {
        vw[0] = __ldg(reinterpret_cast<const float4*>(W + (long)r_  * 256 + k0) + c4_);
        vw[1] = __ldg(reinterpret_cast<const float4*>(W + (long)r2_ * 256 + k0) + c4_);
    };
    auto stage = [&](int buf, const float4 va[2], const float4 vw[2]) {
        const int rr[2] = {r_, r2_};
#pragma unroll
        for (int i = 0; i < 2; i++) {
            As[buf][c4_ * 4 + 0][rr[i]] = (i == 0 ? va[0].x : va[1].x);
            As[buf][c4_ * 4 + 1][rr[i]] = (i == 0 ? va[0].y : va[1].y);
            As[buf][c4_ * 4 + 2][rr[i]] = (i == 0 ? va[0].z : va[1].z);
            As[buf][c4_ * 4 + 3][rr[i]] = (i == 0 ? va[0].w : va[1].w);
            Wsh[buf][c4_ * 4 + 0][rr[i]] = (i == 0 ? vw[0].x : vw[1].x);
            Wsh[buf][c4_ * 4 + 1][rr[i]] = (i == 0 ? vw[0].y : vw[1].y);
            Wsh[buf][c4_ * 4 + 2][rr[i]] = (i == 0 ? vw[0].z : vw[1].z);
            Wsh[buf][c4_ * 4 + 3][rr[i]] = (i == 0 ? vw[0].w : vw[1].w);
        }
    };

    float acc[8][8];
#pragma unroll
    for (int m = 0; m < 8; m++)
#pragma unroll
        for (int nn = 0; nn < 8; nn++) acc[m][nn] = 0.f;

    float4 va[2], vw[2];
    loadA(0, va); loadW(0, vw);
    stage(0, va, vw);
    __syncthreads();

    int buf = 0;
    for (int t = 0; t < 16; t++) {
        float4 na[2], nw[2];
        if (t < 15) {                      // prefetch next tile (overlaps compute)
            loadA((t + 1) * 16, na);
            loadW((t + 1) * 16, nw);
        }

#pragma unroll
        for (int kk = 0; kk < 16; kk++) {
            float4 a0 = *reinterpret_cast<const float4*>(&As[buf][kk][ty * 8]);
            float4 a1 = *reinterpret_cast<const float4*>(&As[buf][kk][ty * 8 + 4]);
            float4 w0 = *reinterpret_cast<const float4*>(&Wsh[buf][kk][tx * 8]);
            float4 w1 = *reinterpret_cast<const float4*>(&Wsh[buf][kk][tx * 8 + 4]);
            float a[8] = {a0.x, a0.y, a0.z, a0.w, a1.x, a1.y, a1.z, a1.w};
            float w[8] = {w0.x, w0.y, w0.z, w0.w, w1.x, w1.y, w1.z, w1.w};
#pragma unroll
            for (int m = 0; m < 8; m++)
#pragma unroll
                for (int nn = 0; nn < 8; nn++) acc[m][nn] = fmaf(a[m], w[nn], acc[m][nn]);
        }

        if (t < 15) {                      // stage into the OTHER buffer; 1 sync
            stage(buf ^ 1, na, nw);
            __syncthreads();
            buf ^= 1;
        }
    }

    // Epilogue: bias (+ReLU), vectorized stores
    const int col0 = tx * 8;
    float bv[8];
#pragma unroll
    for (int nn = 0; nn < 8; nn++) bv[nn] = __ldg(&bias[col0 + nn]);

#pragma unroll
    for (int m = 0; m < 8; m++) {
        int r = row0 + ty * 8 + m;
        if (r < n) {
#pragma unroll
            for (int g = 0; g < 2; g++) {
                float4 o;
                o.x = acc[m][g * 4 + 0] + bv[g * 4 + 0];
                o.y = acc[m][g * 4 + 1] + bv[g * 4 + 1];
                o.z = acc[m][g * 4 + 2] + bv[g * 4 + 2];
                o.w = acc[m][g * 4 + 3] + bv[g * 4 + 3];
                if (RELU) {
                    o.x = fmaxf(o.x, 0.f); o.y = fmaxf(o.y, 0.f);
                    o.z = fmaxf(o.z, 0.f); o.w = fmaxf(o.w, 0.f);
                }
                *reinterpret_cast<float4*>(out + (long)r * DIM + col0 + g * 4) = o;
            }
        }
    }
}

// ---------------------------------------------------------------------------
extern "C" void kernel_launch(void* const* d_in, const int* in_sizes, int n_in,
                              void* d_out, int out_size) {
    const float* x   = (const float*)d_in[0];
    const int*   src = (const int*)  d_in[1];
    const int*   dst = (const int*)  d_in[2];
    const float* W0  = (const float*)d_in[3];
    const float* b0  = (const float*)d_in[4];
    const float* W1  = (const float*)d_in[5];
    const float* b1  = (const float*)d_in[6];
    float* out = (float*)d_out;

    const int n = in_sizes[0] / DIM;
    const int E = in_sizes[1];

    float *p_agg0, *p_agg1, *p_h;
    cudaGetSymbolAddress((void**)&p_agg0, g_agg0);
    cudaGetSymbolAddress((void**)&p_agg1, g_agg1);
    cudaGetSymbolAddress((void**)&p_h,    g_h);

    zero_all_kernel<<<4096, 256>>>();
    deg_kernel<<<(E + 255) / 256, 256>>>(src, E);
    inv_kernel<<<(n + 255) / 256, 256>>>(n);

    // One warp per EPW edges.
    const long n_warps = ((long)E + EPW - 1) / EPW;
    const int scatter_blocks = (int)((n_warps * 32 + 255) / 256);

    // Layer 0
    scatter_kernel<<<scatter_blocks, 256>>>(x, src, dst, p_agg0, E);
    gemm_concat_kernel<true><<<(n + 127) / 128, 256>>>(x, p_agg0, W0, b0, p_h, n);

    // Layer 1
    scatter_kernel<<<scatter_blocks, 256>>>(p_h, src, dst, p_agg1, E);
    gemm_concat_kernel<false><<<(n + 127) / 128, 256>>>(p_h, p_agg1, W1, b1, out, n);
}

// round 8
// speedup vs baseline: 1.8590x; 1.5369x over previous
#include <cuda_runtime.h>
#include <cuda_bf16.h>
#include <cstdint>

// Problem constants (fixed by the dataset)
#define NNODES 100000
#define NEDGES 1600000
#define DIM    128
#define EPW    4      // edges per warp in scatter

// Scratch: __device__ globals (no allocations allowed in kernel_launch).
__device__ float g_deg [NNODES];           // degree, then 1/max(deg,1) in place
__device__ float g_agg0[NNODES * DIM];     // layer-0 aggregation
__device__ float g_agg1[NNODES * DIM];     // layer-1 aggregation
__device__ float g_h   [NNODES * DIM];     // hidden activations

// ---------------------------------------------------------------------------
// Zero scratch accumulators (captured into the graph -> re-zeroed on replay)
// ---------------------------------------------------------------------------
__global__ void zero_all_kernel() {
    const float4 z = make_float4(0.f, 0.f, 0.f, 0.f);
    long i = (long)blockIdx.x * blockDim.x + threadIdx.x;
    long stride = (long)gridDim.x * blockDim.x;
    float4* p0 = reinterpret_cast<float4*>(g_deg);
    float4* p1 = reinterpret_cast<float4*>(g_agg0);
    float4* p2 = reinterpret_cast<float4*>(g_agg1);
    for (long j = i; j < NNODES / 4; j += stride) p0[j] = z;
    for (long j = i; j < (long)NNODES * DIM / 4; j += stride) p1[j] = z;
    for (long j = i; j < (long)NNODES * DIM / 4; j += stride) p2[j] = z;
}

// ---------------------------------------------------------------------------
// Out-degree of src nodes, then invert
// ---------------------------------------------------------------------------
__global__ void deg_kernel(const int* __restrict__ src, int E) {
    int i = blockIdx.x * blockDim.x + threadIdx.x;
    if (i < E) atomicAdd(&g_deg[src[i]], 1.0f);
}

__global__ void inv_kernel(int n) {
    int i = blockIdx.x * blockDim.x + threadIdx.x;
    if (i < n) g_deg[i] = 1.0f / fmaxf(g_deg[i], 1.0f);
}

// ---------------------------------------------------------------------------
// Scatter: agg[dst] += feat[src] * inv_deg[src]   (unchanged from R6 pass)
// ---------------------------------------------------------------------------
__global__ __launch_bounds__(256) void scatter_kernel(
        const float* __restrict__ feat,
        const int* __restrict__ src,
        const int* __restrict__ dst,
        float* __restrict__ agg, int E) {
    const long warp = ((long)blockIdx.x * blockDim.x + threadIdx.x) >> 5;
    const int lane = threadIdx.x & 31;
    const long e0 = warp * EPW;
    if (e0 >= E) return;

    int  s[EPW], d[EPW];
    bool ok[EPW];
#pragma unroll
    for (int i = 0; i < EPW; i++) {
        long e = e0 + i;
        ok[i] = (e < E);
        s[i] = ok[i] ? __ldg(src + e) : 0;
        d[i] = ok[i] ? __ldg(dst + e) : 0;
    }
    float sc[EPW];
#pragma unroll
    for (int i = 0; i < EPW; i++) sc[i] = __ldg(&g_deg[s[i]]);

    float4 v[EPW];
#pragma unroll
    for (int i = 0; i < EPW; i++)
        v[i] = __ldg(reinterpret_cast<const float4*>(feat) + (long)s[i] * 32 + lane);

#pragma unroll
    for (int i = 0; i < EPW; i++) {
        if (!ok[i]) continue;
        float* p = agg + (long)d[i] * DIM + lane * 4;
        asm volatile("red.global.add.v4.f32 [%0], {%1, %2, %3, %4};"
                     :: "l"(p), "f"(v[i].x * sc[i]), "f"(v[i].y * sc[i]),
                        "f"(v[i].z * sc[i]), "f"(v[i].w * sc[i])
                     : "memory");
    }
}

// ===========================================================================
// Tensor-core GEMM via mma.sync (m16n8k8 tf32) — plain compute_103 PTX.
//   out[128-row tile][128] = [A0|A1] (K=256) . W^T + bias
// 8 warps: 4(m) x 2(n); each warp 32x64 = 2x8 fragments, fp32 accum.
// BK=16 k-chunks, double-buffered smem + register prefetch.
// Smem row stride 20 words -> fragment LDS patterns are bank-conflict-free.
// ===========================================================================
#define SSTR 20   // smem row stride in words

__device__ __forceinline__ uint32_t f2tf32(float f) {
    uint32_t u;
    asm("cvt.rna.tf32.f32 %0, %1;" : "=r"(u) : "f"(f));
    return u;
}

__device__ __forceinline__ void mma_tf32(float d[4], const uint32_t a[4],
                                         const uint32_t b[2]) {
    asm volatile(
        "mma.sync.aligned.m16n8k8.row.col.f32.tf32.tf32.f32 "
        "{%0,%1,%2,%3}, {%4,%5,%6,%7}, {%8,%9}, {%0,%1,%2,%3};"
        : "+f"(d[0]), "+f"(d[1]), "+f"(d[2]), "+f"(d[3])
        : "r"(a[0]), "r"(a[1]), "r"(a[2]), "r"(a[3]), "r"(b[0]), "r"(b[1]));
}

template <bool RELU>
__global__ __launch_bounds__(256, 2) void gemm_mma_kernel(
        const float* __restrict__ A0,
        const float* __restrict__ A1,
        const float* __restrict__ W,
        const float* __restrict__ bias,
        float* __restrict__ out, int n) {
    __shared__ uint32_t As [2][128][SSTR];  // As[buf][row][k], tf32 bits
    __shared__ uint32_t Wsh[2][128][SSTR];  // Wsh[buf][j][k]

    const int tid = threadIdx.x;
    const int wid = tid >> 5;
    const int lane = tid & 31;
    const int row0 = blockIdx.x * 128;
    const int warp_m = wid & 3;        // 4 m-groups of 32 rows
    const int warp_n = wid >> 2;       // 2 n-groups of 64 cols
    const int mbase = warp_m * 32;
    const int nbase = warp_n * 64;
    const int lq = lane >> 2;          // lane/4 (0..7)
    const int lr = lane & 3;           // lane%4 (0..3)

    // Per-thread staging coords: 2 float4 per operand per chunk
    const int r_a = tid >> 2, kc = tid & 3;        // first: rows 0..63
    const int r_b = (tid + 256) >> 2;              // second: rows 64..127

    // Prefetch chunk t into registers
    auto fetch = [&](int t, float4 va[2], float4 vw[2]) {
        const float* Asrc = (t < 8) ? A0 : A1;
        const int tk = (t & 7) * 4;                // float4 offset within K-half
        int rg0 = row0 + r_a, rg1 = row0 + r_b;
        va[0] = make_float4(0.f, 0.f, 0.f, 0.f);
        va[1] = make_float4(0.f, 0.f, 0.f, 0.f);
        if (rg0 < n) va[0] = __ldg(reinterpret_cast<const float4*>(Asrc) + (long)rg0 * 32 + tk + kc);
        if (rg1 < n) va[1] = __ldg(reinterpret_cast<const float4*>(Asrc) + (long)rg1 * 32 + tk + kc);
        vw[0] = __ldg(reinterpret_cast<const float4*>(W) + (long)r_a * 64 + t * 4 + kc);
        vw[1] = __ldg(reinterpret_cast<const float4*>(W) + (long)r_b * 64 + t * 4 + kc);
    };
    auto stage = [&](int buf, const float4 va[2], const float4 vw[2]) {
        const int rr[2] = {r_a, r_b};
#pragma unroll
        for (int i = 0; i < 2; i++) {
            const float4& a = va[i];
            const float4& w = vw[i];
            uint4 ua = make_uint4(f2tf32(a.x), f2tf32(a.y), f2tf32(a.z), f2tf32(a.w));
            uint4 uw = make_uint4(f2tf32(w.x), f2tf32(w.y), f2tf32(w.z), f2tf32(w.w));
            *reinterpret_cast<uint4*>(&As [buf][rr[i]][kc * 4]) = ua;
            *reinterpret_cast<uint4*>(&Wsh[buf][rr[i]][kc * 4]) = uw;
        }
    };

    float acc[2][8][4];
#pragma unroll
    for (int mf = 0; mf < 2; mf++)
#pragma unroll
        for (int nf = 0; nf < 8; nf++)
#pragma unroll
            for (int q = 0; q < 4; q++) acc[mf][nf][q] = 0.f;

    float4 va[2], vw[2];
    fetch(0, va, vw);
    stage(0, va, vw);
    __syncthreads();

    int buf = 0;
    for (int t = 0; t < 16; t++) {
        float4 na[2], nw[2];
        if (t < 15) fetch(t + 1, na, nw);   // overlaps with MMA compute below

#pragma unroll
        for (int ks = 0; ks < 2; ks++) {
            const int kofs = ks * 8;
            uint32_t afrag[2][4];
#pragma unroll
            for (int mf = 0; mf < 2; mf++) {
                const int r = mbase + mf * 16;
                afrag[mf][0] = As[buf][r + lq     ][kofs + lr];
                afrag[mf][1] = As[buf][r + 8 + lq ][kofs + lr];
                afrag[mf][2] = As[buf][r + lq     ][kofs + 4 + lr];
                afrag[mf][3] = As[buf][r + 8 + lq ][kofs + 4 + lr];
            }
            uint32_t bfrag[8][2];
#pragma unroll
            for (int nf = 0; nf < 8; nf++) {
                const int c = nbase + nf * 8 + lq;
                bfrag[nf][0] = Wsh[buf][c][kofs + lr];
                bfrag[nf][1] = Wsh[buf][c][kofs + 4 + lr];
            }
#pragma unroll
            for (int mf = 0; mf < 2; mf++)
#pragma unroll
                for (int nf = 0; nf < 8; nf++)
                    mma_tf32(acc[mf][nf], afrag[mf], bfrag[nf]);
        }

        if (t < 15) {
            stage(buf ^ 1, na, nw);
            __syncthreads();
            buf ^= 1;
        }
    }

    // Epilogue: bias (+ReLU). c0,c1 -> (row, col..col+1); c2,c3 -> row+8.
#pragma unroll
    for (int nf = 0; nf < 8; nf++) {
        const int col = nbase + nf * 8 + 2 * lr;
        const float2 bv = *reinterpret_cast<const float2*>(bias + col);
#pragma unroll
        for (int mf = 0; mf < 2; mf++) {
#pragma unroll
            for (int h = 0; h < 2; h++) {   // h=0: rows +0, h=1: rows +8
                const int rg = row0 + mbase + mf * 16 + h * 8 + lq;
                if (rg < n) {
                    float2 o;
                    o.x = acc[mf][nf][h * 2 + 0] + bv.x;
                    o.y = acc[mf][nf][h * 2 + 1] + bv.y;
                    if (RELU) { o.x = fmaxf(o.x, 0.f); o.y = fmaxf(o.y, 0.f); }
                    *reinterpret_cast<float2*>(out + (long)rg * DIM + col) = o;
                }
            }
        }
    }
}

// ---------------------------------------------------------------------------
extern "C" void kernel_launch(void* const* d_in, const int* in_sizes, int n_in,
                              void* d_out, int out_size) {
    const float* x   = (const float*)d_in[0];
    const int*   src = (const int*)  d_in[1];
    const int*   dst = (const int*)  d_in[2];
    const float* W0  = (const float*)d_in[3];
    const float* b0  = (const float*)d_in[4];
    const float* W1  = (const float*)d_in[5];
    const float* b1  = (const float*)d_in[6];
    float* out = (float*)d_out;

    const int n = in_sizes[0] / DIM;
    const int E = in_sizes[1];

    float *p_agg0, *p_agg1, *p_h;
    cudaGetSymbolAddress((void**)&p_agg0, g_agg0);
    cudaGetSymbolAddress((void**)&p_agg1, g_agg1);
    cudaGetSymbolAddress((void**)&p_h,    g_h);

    zero_all_kernel<<<4096, 256>>>();
    deg_kernel<<<(E + 255) / 256, 256>>>(src, E);
    inv_kernel<<<(n + 255) / 256, 256>>>(n);

    const long n_warps = ((long)E + EPW - 1) / EPW;
    const int scatter_blocks = (int)((n_warps * 32 + 255) / 256);
    const int gemm_blocks = (n + 127) / 128;

    // Layer 0
    scatter_kernel<<<scatter_blocks, 256>>>(x, src, dst, p_agg0, E);
    gemm_mma_kernel<true><<<gemm_blocks, 256>>>(x, p_agg0, W0, b0, p_h, n);

    // Layer 1
    scatter_kernel<<<scatter_blocks, 256>>>(p_h, src, dst, p_agg1, E);
    gemm_mma_kernel<false><<<gemm_blocks, 256>>>(p_h, p_agg1, W1, b1, out, n);
}

// round 10
// speedup vs baseline: 1.8787x; 1.0106x over previous
#include <cuda_runtime.h>
#include <cuda_bf16.h>
#include <cstdint>

// Problem constants (fixed by the dataset)
#define NNODES 100000
#define NEDGES 1600000
#define DIM    128

// Scratch: __device__ globals (no allocations allowed in kernel_launch).
__device__ float g_deg   [NNODES];        // out-degree (by src), then 1/max(deg,1)
__device__ int   g_cnt   [NNODES];        // in-degree (by dst) histogram
__device__ int   g_rowptr[NNODES + 1];    // CSR row pointers (by dst)
__device__ int   g_ofs   [NNODES];        // running fill offsets
__device__ int   g_csrc  [NEDGES];        // CSR payload: src node per slot
__device__ float g_agg0  [NNODES * DIM];  // layer-0 aggregation
__device__ float g_agg1  [NNODES * DIM];  // layer-1 aggregation
__device__ float g_h     [NNODES * DIM];  // hidden activations

// ---------------------------------------------------------------------------
// Zero the small per-replay state (deg + cnt only; agg rows are fully written)
// ---------------------------------------------------------------------------
__global__ void zero_small_kernel() {
    int i = blockIdx.x * blockDim.x + threadIdx.x;
    if (i < NNODES) { g_deg[i] = 0.f; g_cnt[i] = 0; }
}

// ---------------------------------------------------------------------------
// Histogram: out-degree by src (float) + in-degree by dst (int)
// ---------------------------------------------------------------------------
__global__ void deg_cnt_kernel(const int* __restrict__ src,
                               const int* __restrict__ dst, int E) {
    int i = blockIdx.x * blockDim.x + threadIdx.x;
    if (i < E) {
        atomicAdd(&g_deg[src[i]], 1.0f);
        atomicAdd(&g_cnt[dst[i]], 1);
    }
}

__global__ void inv_kernel(int n) {
    int i = blockIdx.x * blockDim.x + threadIdx.x;
    if (i < n) g_deg[i] = 1.0f / fmaxf(g_deg[i], 1.0f);
}

// ---------------------------------------------------------------------------
// Single-block exclusive scan of g_cnt -> g_rowptr / g_ofs
// ---------------------------------------------------------------------------
#define SCAN_T 1024
__global__ void scan_kernel(int n) {
    __shared__ int sh[SCAN_T];
    const int t = threadIdx.x;
    const int chunk = (n + SCAN_T - 1) / SCAN_T;
    const int b = t * chunk;
    const int e = min(b + chunk, n);

    int sum = 0;
    for (int i = b; i < e; i++) sum += g_cnt[i];
    sh[t] = sum;
    __syncthreads();

    // Hillis-Steele inclusive scan over the 1024 partials
    for (int off = 1; off < SCAN_T; off <<= 1) {
        int v = (t >= off) ? sh[t - off] : 0;
        __syncthreads();
        sh[t] += v;
        __syncthreads();
    }

    int run = sh[t] - sum;  // exclusive prefix of this thread's chunk
    for (int i = b; i < e; i++) {
        int c = g_cnt[i];
        g_rowptr[i] = run;
        g_ofs[i] = run;
        run += c;
    }
    if (t == SCAN_T - 1) g_rowptr[n] = run;   // == E
}

// ---------------------------------------------------------------------------
// Fill CSR payload: slot per (dst) bucket gets the edge's src id
// ---------------------------------------------------------------------------
__global__ void fill_kernel(const int* __restrict__ src,
                            const int* __restrict__ dst, int E) {
    int i = blockIdx.x * blockDim.x + threadIdx.x;
    if (i < E) {
        int p = atomicAdd(&g_ofs[dst[i]], 1);
        g_csrc[p] = src[i];
    }
}

// ---------------------------------------------------------------------------
// Gather aggregation: agg[v] = sum_{u in inlist(v)} feat[u] * inv_outdeg(u)
// One warp per node, 4-edge ILP batches, single coalesced float4 store.
// No float atomics anywhere.
// ---------------------------------------------------------------------------
__global__ __launch_bounds__(256) void gather_kernel(
        const float* __restrict__ feat,
        float* __restrict__ agg, int n) {
    const int warp = (int)(((long)blockIdx.x * blockDim.x + threadIdx.x) >> 5);
    if (warp >= n) return;
    const int lane = threadIdx.x & 31;
    const int beg = __ldg(&g_rowptr[warp]);
    const int end = __ldg(&g_rowptr[warp + 1]);

    float4 acc = make_float4(0.f, 0.f, 0.f, 0.f);
    int j = beg;
    for (; j + 4 <= end; j += 4) {
        int s0 = __ldg(g_csrc + j + 0);
        int s1 = __ldg(g_csrc + j + 1);
        int s2 = __ldg(g_csrc + j + 2);
        int s3 = __ldg(g_csrc + j + 3);
        float c0 = __ldg(&g_deg[s0]);
        float c1 = __ldg(&g_deg[s1]);
        float c2 = __ldg(&g_deg[s2]);
        float c3 = __ldg(&g_deg[s3]);
        float4 v0 = __ldg(reinterpret_cast<const float4*>(feat) + (long)s0 * 32 + lane);
        float4 v1 = __ldg(reinterpret_cast<const float4*>(feat) + (long)s1 * 32 + lane);
        float4 v2 = __ldg(reinterpret_cast<const float4*>(feat) + (long)s2 * 32 + lane);
        float4 v3 = __ldg(reinterpret_cast<const float4*>(feat) + (long)s3 * 32 + lane);
        acc.x += v0.x * c0; acc.y += v0.y * c0; acc.z += v0.z * c0; acc.w += v0.w * c0;
        acc.x += v1.x * c1; acc.y += v1.y * c1; acc.z += v1.z * c1; acc.w += v1.w * c1;
        acc.x += v2.x * c2; acc.y += v2.y * c2; acc.z += v2.z * c2; acc.w += v2.w * c2;
        acc.x += v3.x * c3; acc.y += v3.y * c3; acc.z += v3.z * c3; acc.w += v3.w * c3;
    }
    for (; j < end; j++) {
        int s = __ldg(g_csrc + j);
        float c = __ldg(&g_deg[s]);
        float4 v = __ldg(reinterpret_cast<const float4*>(feat) + (long)s * 32 + lane);
        acc.x += v.x * c; acc.y += v.y * c; acc.z += v.z * c; acc.w += v.w * c;
    }
    reinterpret_cast<float4*>(agg)[(long)warp * 32 + lane] = acc;
}

// ===========================================================================
// Tensor-core GEMM via mma.sync (m16n8k8 tf32) — unchanged from R8 pass.
//   out[128-row tile][128] = [A0|A1] (K=256) . W^T + bias
// ===========================================================================
#define SSTR 20   // smem row stride in words

__device__ __forceinline__ uint32_t f2tf32(float f) {
    uint32_t u;
    asm("cvt.rna.tf32.f32 %0, %1;" : "=r"(u) : "f"(f));
    return u;
}

__device__ __forceinline__ void mma_tf32(float d[4], const uint32_t a[4],
                                         const uint32_t b[2]) {
    asm volatile(
        "mma.sync.aligned.m16n8k8.row.col.f32.tf32.tf32.f32 "
        "{%0,%1,%2,%3}, {%4,%5,%6,%7}, {%8,%9}, {%0,%1,%2,%3};"
        : "+f"(d[0]), "+f"(d[1]), "+f"(d[2]), "+f"(d[3])
        : "r"(a[0]), "r"(a[1]), "r"(a[2]), "r"(a[3]), "r"(b[0]), "r"(b[1]));
}

template <bool RELU>
__global__ __launch_bounds__(256, 2) void gemm_mma_kernel(
        const float* __restrict__ A0,
        const float* __restrict__ A1,
        const float* __restrict__ W,
        const float* __restrict__ bias,
        float* __restrict__ out, int n) {
    __shared__ uint32_t As [2][128][SSTR];
    __shared__ uint32_t Wsh[2][128][SSTR];

    const int tid = threadIdx.x;
    const int wid = tid >> 5;
    const int lane = tid & 31;
    const int row0 = blockIdx.x * 128;
    const int warp_m = wid & 3;
    const int warp_n = wid >> 2;
    const int mbase = warp_m * 32;
    const int nbase = warp_n * 64;
    const int lq = lane >> 2;
    const int lr = lane & 3;

    const int r_a = tid >> 2, kc = tid & 3;
    const int r_b = (tid + 256) >> 2;

    auto fetch = [&](int t, float4 va[2], float4 vw[2]) {
        const float* Asrc = (t < 8) ? A0 : A1;
        const int tk = (t & 7) * 4;
        int rg0 = row0 + r_a, rg1 = row0 + r_b;
        va[0] = make_float4(0.f, 0.f, 0.f, 0.f);
        va[1] = make_float4(0.f, 0.f, 0.f, 0.f);
        if (rg0 < n) va[0] = __ldg(reinterpret_cast<const float4*>(Asrc) + (long)rg0 * 32 + tk + kc);
        if (rg1 < n) va[1] = __ldg(reinterpret_cast<const float4*>(Asrc) + (long)rg1 * 32 + tk + kc);
        vw[0] = __ldg(reinterpret_cast<const float4*>(W) + (long)r_a * 64 + t * 4 + kc);
        vw[1] = __ldg(reinterpret_cast<const float4*>(W) + (long)r_b * 64 + t * 4 + kc);
    };
    auto stage = [&](int buf, const float4 va[2], const float4 vw[2]) {
        const int rr[2] = {r_a, r_b};
#pragma unroll
        for (int i = 0; i < 2; i++) {
            const float4& a = va[i];
            const float4& w = vw[i];
            uint4 ua = make_uint4(f2tf32(a.x), f2tf32(a.y), f2tf32(a.z), f2tf32(a.w));
            uint4 uw = make_uint4(f2tf32(w.x), f2tf32(w.y), f2tf32(w.z), f2tf32(w.w));
            *reinterpret_cast<uint4*>(&As [buf][rr[i]][kc * 4]) = ua;
            *reinterpret_cast<uint4*>(&Wsh[buf][rr[i]][kc * 4]) = uw;
        }
    };

    float acc[2][8][4];
#pragma unroll
    for (int mf = 0; mf < 2; mf++)
#pragma unroll
        for (int nf = 0; nf < 8; nf++)
#pragma unroll
            for (int q = 0; q < 4; q++) acc[mf][nf][q] = 0.f;

    float4 va[2], vw[2];
    fetch(0, va, vw);
    stage(0, va, vw);
    __syncthreads();

    int buf = 0;
    for (int t = 0; t < 16; t++) {
        float4 na[2], nw[2];
        if (t < 15) fetch(t + 1, na, nw);

#pragma unroll
        for (int ks = 0; ks < 2; ks++) {
            const int kofs = ks * 8;
            uint32_t afrag[2][4];
#pragma unroll
            for (int mf = 0; mf < 2; mf++) {
                const int r = mbase + mf * 16;
                afrag[mf][0] = As[buf][r + lq     ][kofs + lr];
                afrag[mf][1] = As[buf][r + 8 + lq ][kofs + lr];
                afrag[mf][2] = As[buf][r + lq     ][kofs + 4 + lr];
                afrag[mf][3] = As[buf][r + 8 + lq ][kofs + 4 + lr];
            }
            uint32_t bfrag[8][2];
#pragma unroll
            for (int nf = 0; nf < 8; nf++) {
                const int c = nbase + nf * 8 + lq;
                bfrag[nf][0] = Wsh[buf][c][kofs + lr];
                bfrag[nf][1] = Wsh[buf][c][kofs + 4 + lr];
            }
#pragma unroll
            for (int mf = 0; mf < 2; mf++)
#pragma unroll
                for (int nf = 0; nf < 8; nf++)
                    mma_tf32(acc[mf][nf], afrag[mf], bfrag[nf]);
        }

        if (t < 15) {
            stage(buf ^ 1, na, nw);
            __syncthreads();
            buf ^= 1;
        }
    }

#pragma unroll
    for (int nf = 0; nf < 8; nf++) {
        const int col = nbase + nf * 8 + 2 * lr;
        const float2 bv = *reinterpret_cast<const float2*>(bias + col);
#pragma unroll
        for (int mf = 0; mf < 2; mf++) {
#pragma unroll
            for (int h = 0; h < 2; h++) {
                const int rg = row0 + mbase + mf * 16 + h * 8 + lq;
                if (rg < n) {
                    float2 o;
                    o.x = acc[mf][nf][h * 2 + 0] + bv.x;
                    o.y = acc[mf][nf][h * 2 + 1] + bv.y;
                    if (RELU) { o.x = fmaxf(o.x, 0.f); o.y = fmaxf(o.y, 0.f); }
                    *reinterpret_cast<float2*>(out + (long)rg * DIM + col) = o;
                }
            }
        }
    }
}

// ---------------------------------------------------------------------------
extern "C" void kernel_launch(void* const* d_in, const int* in_sizes, int n_in,
                              void* d_out, int out_size) {
    const float* x   = (const float*)d_in[0];
    const int*   src = (const int*)  d_in[1];
    const int*   dst = (const int*)  d_in[2];
    const float* W0  = (const float*)d_in[3];
    const float* b0  = (const float*)d_in[4];
    const float* W1  = (const float*)d_in[5];
    const float* b1  = (const float*)d_in[6];
    float* out = (float*)d_out;

    const int n = in_sizes[0] / DIM;
    const int E = in_sizes[1];

    float *p_agg0, *p_agg1, *p_h;
    cudaGetSymbolAddress((void**)&p_agg0, g_agg0);
    cudaGetSymbolAddress((void**)&p_agg1, g_agg1);
    cudaGetSymbolAddress((void**)&p_h,    g_h);

    // ---- CSR build (per replay; all captured) ----
    zero_small_kernel<<<(NNODES + 255) / 256, 256>>>();
    deg_cnt_kernel<<<(E + 255) / 256, 256>>>(src, dst, E);
    inv_kernel<<<(n + 255) / 256, 256>>>(n);
    scan_kernel<<<1, SCAN_T>>>(n);
    fill_kernel<<<(E + 255) / 256, 256>>>(src, dst, E);

    const int gather_blocks = (int)(((long)n * 32 + 255) / 256);
    const int gemm_blocks = (n + 127) / 128;

    // Layer 0
    gather_kernel<<<gather_blocks, 256>>>(x, p_agg0, n);
    gemm_mma_kernel<true><<<gemm_blocks, 256>>>(x, p_agg0, W0, b0, p_h, n);

    // Layer 1
    gather_kernel<<<gather_blocks, 256>>>(p_h, p_agg1, n);
    gemm_mma_kernel<false><<<gemm_blocks, 256>>>(p_h, p_agg1, W1, b1, out, n);
}

// round 11
// speedup vs baseline: 2.8342x; 1.5086x over previous
#include <cuda_runtime.h>
#include <cuda_bf16.h>
#include <cstdint>

// Problem constants (fixed by the dataset)
#define NNODES 100000
#define NEDGES 1600000
#define DIM    128

// Scan config: 3-phase decoupled scan
#define SB 256                              // threads per scan block
#define SE 512                              // elements per scan block
#define NSB ((NNODES + SE - 1) / SE)        // 196 blocks (<= 256)

// Scratch: __device__ globals (no allocations allowed in kernel_launch).
__device__ float g_deg   [NNODES];        // out-degree (by src), then 1/max(deg,1)
__device__ int   g_cnt   [NNODES];        // in-degree (by dst) histogram
__device__ int   g_rowptr[NNODES + 1];    // CSR row pointers (by dst)
__device__ int   g_ofs   [NNODES];        // running fill offsets
__device__ int   g_csrc  [NEDGES];        // CSR payload: src node per slot
__device__ int   g_bsum  [NSB];           // per-block partial sums
__device__ int   g_boff  [NSB];           // per-block exclusive offsets
__device__ float g_agg0  [NNODES * DIM];  // layer-0 aggregation
__device__ float g_agg1  [NNODES * DIM];  // layer-1 aggregation
__device__ float g_h     [NNODES * DIM];  // hidden activations

// ---------------------------------------------------------------------------
// Zero the small per-replay state (deg + cnt only; agg rows are fully written)
// ---------------------------------------------------------------------------
__global__ void zero_small_kernel() {
    int i = blockIdx.x * blockDim.x + threadIdx.x;
    if (i < NNODES) { g_deg[i] = 0.f; g_cnt[i] = 0; }
}

// ---------------------------------------------------------------------------
// Histogram: out-degree by src (float) + in-degree by dst (int)
// ---------------------------------------------------------------------------
__global__ void deg_cnt_kernel(const int* __restrict__ src,
                               const int* __restrict__ dst, int E) {
    int i = blockIdx.x * blockDim.x + threadIdx.x;
    if (i < E) {
        atomicAdd(&g_deg[src[i]], 1.0f);
        atomicAdd(&g_cnt[dst[i]], 1);
    }
}

__global__ void inv_kernel(int n) {
    int i = blockIdx.x * blockDim.x + threadIdx.x;
    if (i < n) g_deg[i] = 1.0f / fmaxf(g_deg[i], 1.0f);
}

// ---------------------------------------------------------------------------
// Phase 1: per-block reduction of 512 counts -> g_bsum[b]
// ---------------------------------------------------------------------------
__global__ void scan_partial(int n) {
    __shared__ int sh[SB];
    const int b = blockIdx.x, t = threadIdx.x;
    const int i0 = b * SE + t * 2;
    int c0 = (i0     < n) ? g_cnt[i0]     : 0;
    int c1 = (i0 + 1 < n) ? g_cnt[i0 + 1] : 0;
    sh[t] = c0 + c1;
    __syncthreads();
#pragma unroll
    for (int off = SB / 2; off > 0; off >>= 1) {
        if (t < off) sh[t] += sh[t + off];
        __syncthreads();
    }
    if (t == 0) g_bsum[b] = sh[0];
}

// ---------------------------------------------------------------------------
// Phase 2: one block scans the <=256 block sums -> g_boff (exclusive),
// and writes g_rowptr[n] = total (== E)
// ---------------------------------------------------------------------------
__global__ void scan_top(int n, int nsb) {
    __shared__ int sh[SB];
    const int t = threadIdx.x;
    int v = (t < nsb) ? g_bsum[t] : 0;
    sh[t] = v;
    __syncthreads();
#pragma unroll
    for (int off = 1; off < SB; off <<= 1) {
        int u = (t >= off) ? sh[t - off] : 0;
        __syncthreads();
        sh[t] += u;
        __syncthreads();
    }
    if (t < nsb) g_boff[t] = sh[t] - v;          // exclusive prefix
    if (t == SB - 1) g_rowptr[n] = sh[SB - 1];   // total = E
}

// ---------------------------------------------------------------------------
// Phase 3: per-block exclusive scan + block offset -> rowptr / ofs
// ---------------------------------------------------------------------------
__global__ void scan_final(int n) {
    __shared__ int sh[SB];
    const int b = blockIdx.x, t = threadIdx.x;
    const int i0 = b * SE + t * 2;
    int c0 = (i0     < n) ? g_cnt[i0]     : 0;
    int c1 = (i0 + 1 < n) ? g_cnt[i0 + 1] : 0;
    int s = c0 + c1;
    sh[t] = s;
    __syncthreads();
#pragma unroll
    for (int off = 1; off < SB; off <<= 1) {
        int u = (t >= off) ? sh[t - off] : 0;
        __syncthreads();
        sh[t] += u;
        __syncthreads();
    }
    int run = g_boff[b] + sh[t] - s;             // exclusive within grid
    if (i0 < n)     { g_rowptr[i0]     = run;      g_ofs[i0]     = run;      }
    if (i0 + 1 < n) { g_rowptr[i0 + 1] = run + c0; g_ofs[i0 + 1] = run + c0; }
}

// ---------------------------------------------------------------------------
// Fill CSR payload: slot per (dst) bucket gets the edge's src id
// ---------------------------------------------------------------------------
__global__ void fill_kernel(const int* __restrict__ src,
                            const int* __restrict__ dst, int E) {
    int i = blockIdx.x * blockDim.x + threadIdx.x;
    if (i < E) {
        int p = atomicAdd(&g_ofs[dst[i]], 1);
        g_csrc[p] = src[i];
    }
}

// ---------------------------------------------------------------------------
// Gather aggregation: agg[v] = sum_{u in inlist(v)} feat[u] * inv_outdeg(u)
// One warp per node, 4-edge ILP batches, single coalesced float4 store.
// ---------------------------------------------------------------------------
__global__ __launch_bounds__(256) void gather_kernel(
        const float* __restrict__ feat,
        float* __restrict__ agg, int n) {
    const int warp = (int)(((long)blockIdx.x * blockDim.x + threadIdx.x) >> 5);
    if (warp >= n) return;
    const int lane = threadIdx.x & 31;
    const int beg = __ldg(&g_rowptr[warp]);
    const int end = __ldg(&g_rowptr[warp + 1]);

    float4 acc = make_float4(0.f, 0.f, 0.f, 0.f);
    int j = beg;
    for (; j + 4 <= end; j += 4) {
        int s0 = __ldg(g_csrc + j + 0);
        int s1 = __ldg(g_csrc + j + 1);
        int s2 = __ldg(g_csrc + j + 2);
        int s3 = __ldg(g_csrc + j + 3);
        float c0 = __ldg(&g_deg[s0]);
        float c1 = __ldg(&g_deg[s1]);
        float c2 = __ldg(&g_deg[s2]);
        float c3 = __ldg(&g_deg[s3]);
        float4 v0 = __ldg(reinterpret_cast<const float4*>(feat) + (long)s0 * 32 + lane);
        float4 v1 = __ldg(reinterpret_cast<const float4*>(feat) + (long)s1 * 32 + lane);
        float4 v2 = __ldg(reinterpret_cast<const float4*>(feat) + (long)s2 * 32 + lane);
        float4 v3 = __ldg(reinterpret_cast<const float4*>(feat) + (long)s3 * 32 + lane);
        acc.x += v0.x * c0; acc.y += v0.y * c0; acc.z += v0.z * c0; acc.w += v0.w * c0;
        acc.x += v1.x * c1; acc.y += v1.y * c1; acc.z += v1.z * c1; acc.w += v1.w * c1;
        acc.x += v2.x * c2; acc.y += v2.y * c2; acc.z += v2.z * c2; acc.w += v2.w * c2;
        acc.x += v3.x * c3; acc.y += v3.y * c3; acc.z += v3.z * c3; acc.w += v3.w * c3;
    }
    for (; j < end; j++) {
        int s = __ldg(g_csrc + j);
        float c = __ldg(&g_deg[s]);
        float4 v = __ldg(reinterpret_cast<const float4*>(feat) + (long)s * 32 + lane);
        acc.x += v.x * c; acc.y += v.y * c; acc.z += v.z * c; acc.w += v.w * c;
    }
    reinterpret_cast<float4*>(agg)[(long)warp * 32 + lane] = acc;
}

// ===========================================================================
// Tensor-core GEMM via mma.sync (m16n8k8 tf32) — unchanged from R8/R10 pass.
//   out[128-row tile][128] = [A0|A1] (K=256) . W^T + bias
// ===========================================================================
#define SSTR 20   // smem row stride in words

__device__ __forceinline__ uint32_t f2tf32(float f) {
    uint32_t u;
    asm("cvt.rna.tf32.f32 %0, %1;" : "=r"(u) : "f"(f));
    return u;
}

__device__ __forceinline__ void mma_tf32(float d[4], const uint32_t a[4],
                                         const uint32_t b[2]) {
    asm volatile(
        "mma.sync.aligned.m16n8k8.row.col.f32.tf32.tf32.f32 "
        "{%0,%1,%2,%3}, {%4,%5,%6,%7}, {%8,%9}, {%0,%1,%2,%3};"
        : "+f"(d[0]), "+f"(d[1]), "+f"(d[2]), "+f"(d[3])
        : "r"(a[0]), "r"(a[1]), "r"(a[2]), "r"(a[3]), "r"(b[0]), "r"(b[1]));
}

template <bool RELU>
__global__ __launch_bounds__(256, 2) void gemm_mma_kernel(
        const float* __restrict__ A0,
        const float* __restrict__ A1,
        const float* __restrict__ W,
        const float* __restrict__ bias,
        float* __restrict__ out, int n) {
    __shared__ uint32_t As [2][128][SSTR];
    __shared__ uint32_t Wsh[2][128][SSTR];

    const int tid = threadIdx.x;
    const int wid = tid >> 5;
    const int lane = tid & 31;
    const int row0 = blockIdx.x * 128;
    const int warp_m = wid & 3;
    const int warp_n = wid >> 2;
    const int mbase = warp_m * 32;
    const int nbase = warp_n * 64;
    const int lq = lane >> 2;
    const int lr = lane & 3;

    const int r_a = tid >> 2, kc = tid & 3;
    const int r_b = (tid + 256) >> 2;

    auto fetch = [&](int t, float4 va[2], float4 vw[2]) {
        const float* Asrc = (t < 8) ? A0 : A1;
        const int tk = (t & 7) * 4;
        int rg0 = row0 + r_a, rg1 = row0 + r_b;
        va[0] = make_float4(0.f, 0.f, 0.f, 0.f);
        va[1] = make_float4(0.f, 0.f, 0.f, 0.f);
        if (rg0 < n) va[0] = __ldg(reinterpret_cast<const float4*>(Asrc) + (long)rg0 * 32 + tk + kc);
        if (rg1 < n) va[1] = __ldg(reinterpret_cast<const float4*>(Asrc) + (long)rg1 * 32 + tk + kc);
        vw[0] = __ldg(reinterpret_cast<const float4*>(W) + (long)r_a * 64 + t * 4 + kc);
        vw[1] = __ldg(reinterpret_cast<const float4*>(W) + (long)r_b * 64 + t * 4 + kc);
    };
    auto stage = [&](int buf, const float4 va[2], const float4 vw[2]) {
        const int rr[2] = {r_a, r_b};
#pragma unroll
        for (int i = 0; i < 2; i++) {
            const float4& a = va[i];
            const float4& w = vw[i];
            uint4 ua = make_uint4(f2tf32(a.x), f2tf32(a.y), f2tf32(a.z), f2tf32(a.w));
            uint4 uw = make_uint4(f2tf32(w.x), f2tf32(w.y), f2tf32(w.z), f2tf32(w.w));
            *reinterpret_cast<uint4*>(&As [buf][rr[i]][kc * 4]) = ua;
            *reinterpret_cast<uint4*>(&Wsh[buf][rr[i]][kc * 4]) = uw;
        }
    };

    float acc[2][8][4];
#pragma unroll
    for (int mf = 0; mf < 2; mf++)
#pragma unroll
        for (int nf = 0; nf < 8; nf++)
#pragma unroll
            for (int q = 0; q < 4; q++) acc[mf][nf][q] = 0.f;

    float4 va[2], vw[2];
    fetch(0, va, vw);
    stage(0, va, vw);
    __syncthreads();

    int buf = 0;
    for (int t = 0; t < 16; t++) {
        float4 na[2], nw[2];
        if (t < 15) fetch(t + 1, na, nw);

#pragma unroll
        for (int ks = 0; ks < 2; ks++) {
            const int kofs = ks * 8;
            uint32_t afrag[2][4];
#pragma unroll
            for (int mf = 0; mf < 2; mf++) {
                const int r = mbase + mf * 16;
                afrag[mf][0] = As[buf][r + lq     ][kofs + lr];
                afrag[mf][1] = As[buf][r + 8 + lq ][kofs + lr];
                afrag[mf][2] = As[buf][r + lq     ][kofs + 4 + lr];
                afrag[mf][3] = As[buf][r + 8 + lq ][kofs + 4 + lr];
            }
            uint32_t bfrag[8][2];
#pragma unroll
            for (int nf = 0; nf < 8; nf++) {
                const int c = nbase + nf * 8 + lq;
                bfrag[nf][0] = Wsh[buf][c][kofs + lr];
                bfrag[nf][1] = Wsh[buf][c][kofs + 4 + lr];
            }
#pragma unroll
            for (int mf = 0; mf < 2; mf++)
#pragma unroll
                for (int nf = 0; nf < 8; nf++)
                    mma_tf32(acc[mf][nf], afrag[mf], bfrag[nf]);
        }

        if (t < 15) {
            stage(buf ^ 1, na, nw);
            __syncthreads();
            buf ^= 1;
        }
    }

#pragma unroll
    for (int nf = 0; nf < 8; nf++) {
        const int col = nbase + nf * 8 + 2 * lr;
        const float2 bv = *reinterpret_cast<const float2*>(bias + col);
#pragma unroll
        for (int mf = 0; mf < 2; mf++) {
#pragma unroll
            for (int h = 0; h < 2; h++) {
                const int rg = row0 + mbase + mf * 16 + h * 8 + lq;
                if (rg < n) {
                    float2 o;
                    o.x = acc[mf][nf][h * 2 + 0] + bv.x;
                    o.y = acc[mf][nf][h * 2 + 1] + bv.y;
                    if (RELU) { o.x = fmaxf(o.x, 0.f); o.y = fmaxf(o.y, 0.f); }
                    *reinterpret_cast<float2*>(out + (long)rg * DIM + col) = o;
                }
            }
        }
    }
}

// ---------------------------------------------------------------------------
extern "C" void kernel_launch(void* const* d_in, const int* in_sizes, int n_in,
                              void* d_out, int out_size) {
    const float* x   = (const float*)d_in[0];
    const int*   src = (const int*)  d_in[1];
    const int*   dst = (const int*)  d_in[2];
    const float* W0  = (const float*)d_in[3];
    const float* b0  = (const float*)d_in[4];
    const float* W1  = (const float*)d_in[5];
    const float* b1  = (const float*)d_in[6];
    float* out = (float*)d_out;

    const int n = in_sizes[0] / DIM;
    const int E = in_sizes[1];

    float *p_agg0, *p_agg1, *p_h;
    cudaGetSymbolAddress((void**)&p_agg0, g_agg0);
    cudaGetSymbolAddress((void**)&p_agg1, g_agg1);
    cudaGetSymbolAddress((void**)&p_h,    g_h);

    const int nsb = (n + SE - 1) / SE;      // scan blocks (<= NSB <= 256)

    // ---- CSR build (per replay; all captured) ----
    zero_small_kernel<<<(NNODES + 255) / 256, 256>>>();
    deg_cnt_kernel<<<(E + 255) / 256, 256>>>(src, dst, E);
    inv_kernel<<<(n + 255) / 256, 256>>>(n);
    scan_partial<<<nsb, SB>>>(n);
    scan_top<<<1, SB>>>(n, nsb);
    scan_final<<<nsb, SB>>>(n);
    fill_kernel<<<(E + 255) / 256, 256>>>(src, dst, E);

    const int gather_blocks = (int)(((long)n * 32 + 255) / 256);
    const int gemm_blocks = (n + 127) / 128;

    // Layer 0
    gather_kernel<<<gather_blocks, 256>>>(x, p_agg0, n);
    gemm_mma_kernel<true><<<gemm_blocks, 256>>>(x, p_agg0, W0, b0, p_h, n);

    // Layer 1
    gather_kernel<<<gather_blocks, 256>>>(p_h, p_agg1, n);
    gemm_mma_kernel<false><<<gemm_blocks, 256>>>(p_h, p_agg1, W1, b1, out, n);
}

// round 13
// speedup vs baseline: 2.9881x; 1.0543x over previous
#include <cuda_runtime.h>
#include <cuda_bf16.h>
#include <cstdint>

// Problem constants (fixed by the dataset)
#define NNODES 100000
#define NEDGES 1600000
#define DIM    128

// Scan config: 3-phase decoupled scan
#define SB 256                              // threads per scan block
#define SE 512                              // elements per scan block
#define NSB ((NNODES + SE - 1) / SE)        // 196 blocks (<= 256)

// Scratch: __device__ globals (no allocations allowed in kernel_launch).
__device__ float g_deg   [NNODES];        // out-degree (by src), then 1/max(deg,1)
__device__ int   g_cnt   [NNODES];        // in-degree (by dst) histogram
__device__ int   g_rowptr[NNODES + 1];    // CSR row pointers (by dst)
__device__ int   g_ofs   [NNODES];        // running fill offsets
__device__ int   g_csrc  [NEDGES];        // CSR payload: src node per slot
__device__ float g_cscale[NEDGES];        // CSR payload: 1/outdeg(src) per slot
__device__ int   g_bsum  [NSB];           // per-block partial sums
__device__ int   g_boff  [NSB];           // per-block exclusive offsets
__device__ float g_agg0  [NNODES * DIM];  // layer-0 aggregation
__device__ float g_agg1  [NNODES * DIM];  // layer-1 aggregation
__device__ float g_h     [NNODES * DIM];  // hidden activations

// ---------------------------------------------------------------------------
// Zero the small per-replay state (deg + cnt only; agg rows are fully written)
// ---------------------------------------------------------------------------
__global__ void zero_small_kernel() {
    int i = blockIdx.x * blockDim.x + threadIdx.x;
    if (i < NNODES) { g_deg[i] = 0.f; g_cnt[i] = 0; }
}

// ---------------------------------------------------------------------------
// Histogram: out-degree by src (float) + in-degree by dst (int)
// ---------------------------------------------------------------------------
__global__ void deg_cnt_kernel(const int* __restrict__ src,
                               const int* __restrict__ dst, int E) {
    int i = blockIdx.x * blockDim.x + threadIdx.x;
    if (i < E) {
        atomicAdd(&g_deg[src[i]], 1.0f);
        atomicAdd(&g_cnt[dst[i]], 1);
    }
}

// ---------------------------------------------------------------------------
// Phase 1: per-block reduction of 512 counts -> g_bsum[b].
// Also inverts g_deg in the same index range (fused former inv_kernel).
// ---------------------------------------------------------------------------
__global__ void scan_partial(int n) {
    __shared__ int sh[SB];
    const int b = blockIdx.x, t = threadIdx.x;
    const int i0 = b * SE + t * 2;
    int c0 = (i0     < n) ? g_cnt[i0]     : 0;
    int c1 = (i0 + 1 < n) ? g_cnt[i0 + 1] : 0;
    if (i0     < n) g_deg[i0]     = 1.0f / fmaxf(g_deg[i0],     1.0f);
    if (i0 + 1 < n) g_deg[i0 + 1] = 1.0f / fmaxf(g_deg[i0 + 1], 1.0f);
    sh[t] = c0 + c1;
    __syncthreads();
#pragma unroll
    for (int off = SB / 2; off > 0; off >>= 1) {
        if (t < off) sh[t] += sh[t + off];
        __syncthreads();
    }
    if (t == 0) g_bsum[b] = sh[0];
}

// ---------------------------------------------------------------------------
// Phase 2: one block scans the <=256 block sums -> g_boff (exclusive),
// and writes g_rowptr[n] = total (== E)
// ---------------------------------------------------------------------------
__global__ void scan_top(int n, int nsb) {
    __shared__ int sh[SB];
    const int t = threadIdx.x;
    int v = (t < nsb) ? g_bsum[t] : 0;
    sh[t] = v;
    __syncthreads();
#pragma unroll
    for (int off = 1; off < SB; off <<= 1) {
        int u = (t >= off) ? sh[t - off] : 0;
        __syncthreads();
        sh[t] += u;
        __syncthreads();
    }
    if (t < nsb) g_boff[t] = sh[t] - v;          // exclusive prefix
    if (t == SB - 1) g_rowptr[n] = sh[SB - 1];   // total = E
}

// ---------------------------------------------------------------------------
// Phase 3: per-block exclusive scan + block offset -> rowptr / ofs
// ---------------------------------------------------------------------------
__global__ void scan_final(int n) {
    __shared__ int sh[SB];
    const int b = blockIdx.x, t = threadIdx.x;
    const int i0 = b * SE + t * 2;
    int c0 = (i0     < n) ? g_cnt[i0]     : 0;
    int c1 = (i0 + 1 < n) ? g_cnt[i0 + 1] : 0;
    int s = c0 + c1;
    sh[t] = s;
    __syncthreads();
#pragma unroll
    for (int off = 1; off < SB; off <<= 1) {
        int u = (t >= off) ? sh[t - off] : 0;
        __syncthreads();
        sh[t] += u;
        __syncthreads();
    }
    int run = g_boff[b] + sh[t] - s;             // exclusive within grid
    if (i0 < n)     { g_rowptr[i0]     = run;      g_ofs[i0]     = run;      }
    if (i0 + 1 < n) { g_rowptr[i0 + 1] = run + c0; g_ofs[i0 + 1] = run + c0; }
}

// ---------------------------------------------------------------------------
// Fill CSR payload: slot per (dst) bucket gets (src, 1/outdeg(src))
// ---------------------------------------------------------------------------
__global__ void fill_kernel(const int* __restrict__ src,
                            const int* __restrict__ dst, int E) {
    int i = blockIdx.x * blockDim.x + threadIdx.x;
    if (i < E) {
        int s = src[i];
        int p = atomicAdd(&g_ofs[dst[i]], 1);
        g_csrc[p] = s;
        g_cscale[p] = __ldg(&g_deg[s]);   // already inverted
    }
}

// ---------------------------------------------------------------------------
// Gather aggregation: agg[v] = sum_{u in inlist(v)} feat[u] * scale[u]
// One warp per node, 4-edge ILP batches, single coalesced float4 store.
// ---------------------------------------------------------------------------
__global__ __launch_bounds__(256) void gather_kernel(
        const float* __restrict__ feat,
        float* __restrict__ agg, int n) {
    const int warp = (int)(((long)blockIdx.x * blockDim.x + threadIdx.x) >> 5);
    if (warp >= n) return;
    const int lane = threadIdx.x & 31;
    const int beg = __ldg(&g_rowptr[warp]);
    const int end = __ldg(&g_rowptr[warp + 1]);

    float4 acc = make_float4(0.f, 0.f, 0.f, 0.f);
    int j = beg;
    for (; j + 4 <= end; j += 4) {
        int s0 = __ldg(g_csrc + j + 0);
        int s1 = __ldg(g_csrc + j + 1);
        int s2 = __ldg(g_csrc + j + 2);
        int s3 = __ldg(g_csrc + j + 3);
        float c0 = __ldg(g_cscale + j + 0);
        float c1 = __ldg(g_cscale + j + 1);
        float c2 = __ldg(g_cscale + j + 2);
        float c3 = __ldg(g_cscale + j + 3);
        float4 v0 = __ldg(reinterpret_cast<const float4*>(feat) + (long)s0 * 32 + lane);
        float4 v1 = __ldg(reinterpret_cast<const float4*>(feat) + (long)s1 * 32 + lane);
        float4 v2 = __ldg(reinterpret_cast<const float4*>(feat) + (long)s2 * 32 + lane);
        float4 v3 = __ldg(reinterpret_cast<const float4*>(feat) + (long)s3 * 32 + lane);
        acc.x += v0.x * c0; acc.y += v0.y * c0; acc.z += v0.z * c0; acc.w += v0.w * c0;
        acc.x += v1.x * c1; acc.y += v1.y * c1; acc.z += v1.z * c1; acc.w += v1.w * c1;
        acc.x += v2.x * c2; acc.y += v2.y * c2; acc.z += v2.z * c2; acc.w += v2.w * c2;
        acc.x += v3.x * c3; acc.y += v3.y * c3; acc.z += v3.z * c3; acc.w += v3.w * c3;
    }
    for (; j < end; j++) {
        int s = __ldg(g_csrc + j);
        float c = __ldg(g_cscale + j);
        float4 v = __ldg(reinterpret_cast<const float4*>(feat) + (long)s * 32 + lane);
        acc.x += v.x * c; acc.y += v.y * c; acc.z += v.z * c; acc.w += v.w * c;
    }
    reinterpret_cast<float4*>(agg)[(long)warp * 32 + lane] = acc;
}

// ===========================================================================
// Tensor-core GEMM via mma.sync (m16n8k8 tf32).
//   out[128-row tile][128] = [A0|A1] (K=256) . W^T + bias
// 4 warps, each 64x64 (4m x 8n fragments): 32 LDS.32 per 32 MMAs (was 1.5/MMA
// with 8 warps x 32x64) -> smem crossbar pressure cut by a third.
// ===========================================================================
#define SSTR 20   // smem row stride in words

__device__ __forceinline__ uint32_t f2tf32(float f) {
    uint32_t u;
    asm("cvt.rna.tf32.f32 %0, %1;" : "=r"(u) : "f"(f));
    return u;
}

__device__ __forceinline__ void mma_tf32(float d[4], const uint32_t a[4],
                                         const uint32_t b[2]) {
    asm volatile(
        "mma.sync.aligned.m16n8k8.row.col.f32.tf32.tf32.f32 "
        "{%0,%1,%2,%3}, {%4,%5,%6,%7}, {%8,%9}, {%0,%1,%2,%3};"
        : "+f"(d[0]), "+f"(d[1]), "+f"(d[2]), "+f"(d[3])
        : "r"(a[0]), "r"(a[1]), "r"(a[2]), "r"(a[3]), "r"(b[0]), "r"(b[1]));
}

template <bool RELU>
__global__ __launch_bounds__(128, 2) void gemm_mma_kernel(
        const float* __restrict__ A0,
        const float* __restrict__ A1,
        const float* __restrict__ W,
        const float* __restrict__ bias,
        float* __restrict__ out, int n) {
    __shared__ uint32_t As [2][128][SSTR];
    __shared__ uint32_t Wsh[2][128][SSTR];

    const int tid = threadIdx.x;
    const int wid = tid >> 5;          // 0..3
    const int lane = tid & 31;
    const int row0 = blockIdx.x * 128;
    const int mbase = (wid & 1) * 64;  // warp_m
    const int nbase = (wid >> 1) * 64; // warp_n
    const int lq = lane >> 2;
    const int lr = lane & 3;

    const int r_a = tid >> 2, kc = tid & 3;   // rows r_a+32i, word group kc

    auto fetch = [&](int t, float4 va[4], float4 vw[4]) {
        const float* Asrc = (t < 8) ? A0 : A1;
        const int tk = (t & 7) * 4;
#pragma unroll
        for (int i = 0; i < 4; i++) {
            int r = r_a + 32 * i;
            int rg = row0 + r;
            va[i] = make_float4(0.f, 0.f, 0.f, 0.f);
            if (rg < n)
                va[i] = __ldg(reinterpret_cast<const float4*>(Asrc) + (long)rg * 32 + tk + kc);
            vw[i] = __ldg(reinterpret_cast<const float4*>(W) + (long)r * 64 + t * 4 + kc);
        }
    };
    auto stage = [&](int buf, const float4 va[4], const float4 vw[4]) {
#pragma unroll
        for (int i = 0; i < 4; i++) {
            int r = r_a + 32 * i;
            uint4 ua = make_uint4(f2tf32(va[i].x), f2tf32(va[i].y),
                                  f2tf32(va[i].z), f2tf32(va[i].w));
            uint4 uw = make_uint4(f2tf32(vw[i].x), f2tf32(vw[i].y),
                                  f2tf32(vw[i].z), f2tf32(vw[i].w));
            *reinterpret_cast<uint4*>(&As [buf][r][kc * 4]) = ua;
            *reinterpret_cast<uint4*>(&Wsh[buf][r][kc * 4]) = uw;
        }
    };

    float acc[4][8][4];
#pragma unroll
    for (int mf = 0; mf < 4; mf++)
#pragma unroll
        for (int nf = 0; nf < 8; nf++)
#pragma unroll
            for (int q = 0; q < 4; q++) acc[mf][nf][q] = 0.f;

    float4 va[4], vw[4];
    fetch(0, va, vw);
    stage(0, va, vw);
    __syncthreads();

    int buf = 0;
    for (int t = 0; t < 16; t++) {
        float4 na[4], nw[4];
        if (t < 15) fetch(t + 1, na, nw);

#pragma unroll
        for (int ks = 0; ks < 2; ks++) {
            const int kofs = ks * 8;
            uint32_t afrag[4][4];
#pragma unroll
            for (int mf = 0; mf < 4; mf++) {
                const int r = mbase + mf * 16;
                afrag[mf][0] = As[buf][r + lq     ][kofs + lr];
                afrag[mf][1] = As[buf][r + 8 + lq ][kofs + lr];
                afrag[mf][2] = As[buf][r + lq     ][kofs + 4 + lr];
                afrag[mf][3] = As[buf][r + 8 + lq ][kofs + 4 + lr];
            }
            uint32_t bfrag[8][2];
#pragma unroll
            for (int nf = 0; nf < 8; nf++) {
                const int c = nbase + nf * 8 + lq;
                bfrag[nf][0] = Wsh[buf][c][kofs + lr];
                bfrag[nf][1] = Wsh[buf][c][kofs + 4 + lr];
            }
#pragma unroll
            for (int mf = 0; mf < 4; mf++)
#pragma unroll
                for (int nf = 0; nf < 8; nf++)
                    mma_tf32(acc[mf][nf], afrag[mf], bfrag[nf]);
        }

        if (t < 15) {
            stage(buf ^ 1, na, nw);
            __syncthreads();
            buf ^= 1;
        }
    }

#pragma unroll
    for (int nf = 0; nf < 8; nf++) {
        const int col = nbase + nf * 8 + 2 * lr;
        const float2 bv = *reinterpret_cast<const float2*>(bias + col);
#pragma unroll
        for (int mf = 0; mf < 4; mf++) {
#pragma unroll
            for (int h = 0; h < 2; h++) {
                const int rg = row0 + mbase + mf * 16 + h * 8 + lq;
                if (rg < n) {
                    float2 o;
                    o.x = acc[mf][nf][h * 2 + 0] + bv.x;
                    o.y = acc[mf][nf][h * 2 + 1] + bv.y;
                    if (RELU) { o.x = fmaxf(o.x, 0.f); o.y = fmaxf(o.y, 0.f); }
                    *reinterpret_cast<float2*>(out + (long)rg * DIM + col) = o;
                }
            }
        }
    }
}

// ---------------------------------------------------------------------------
extern "C" void kernel_launch(void* const* d_in, const int* in_sizes, int n_in,
                              void* d_out, int out_size) {
    const float* x   = (const float*)d_in[0];
    const int*   src = (const int*)  d_in[1];
    const int*   dst = (const int*)  d_in[2];
    const float* W0  = (const float*)d_in[3];
    const float* b0  = (const float*)d_in[4];
    const float* W1  = (const float*)d_in[5];
    const float* b1  = (const float*)d_in[6];
    float* out = (float*)d_out;

    const int n = in_sizes[0] / DIM;
    const int E = in_sizes[1];

    float *p_agg0, *p_agg1, *p_h;
    cudaGetSymbolAddress((void**)&p_agg0, g_agg0);
    cudaGetSymbolAddress((void**)&p_agg1, g_agg1);
    cudaGetSymbolAddress((void**)&p_h,    g_h);

    const int nsb = (n + SE - 1) / SE;      // scan blocks (<= NSB <= 256)

    // ---- CSR build (per replay; all captured) ----
    zero_small_kernel<<<(NNODES + 255) / 256, 256>>>();
    deg_cnt_kernel<<<(E + 255) / 256, 256>>>(src, dst, E);
    scan_partial<<<nsb, SB>>>(n);           // also inverts g_deg
    scan_top<<<1, SB>>>(n, nsb);
    scan_final<<<nsb, SB>>>(n);
    fill_kernel<<<(E + 255) / 256, 256>>>(src, dst, E);

    const int gather_blocks = (int)(((long)n * 32 + 255) / 256);
    const int gemm_blocks = (n + 127) / 128;

    // Layer 0
    gather_kernel<<<gather_blocks, 256>>>(x, p_agg0, n);
    gemm_mma_kernel<true><<<gemm_blocks, 128>>>(x, p_agg0, W0, b0, p_h, n);

    // Layer 1
    gather_kernel<<<gather_blocks, 256>>>(p_h, p_agg1, n);
    gemm_mma_kernel<false><<<gemm_blocks, 128>>>(p_h, p_agg1, W1, b1, out, n);
}